// round 1
// baseline (speedup 1.0000x reference)
#include <cuda_runtime.h>

#define B_TOTAL    32768
#define NUM_IN     6
#define NUM_MFS    3
#define NUM_RULES  729            // 3^6
#define BLOCK      224            // 7 warps
#define GRID       147            // 147*224 = 32928 >= 32768

// packed f32x2 fma: acc = a*b + acc   (Blackwell fp32x2 pipe, 2 FMAs/instr)
__device__ __forceinline__ void fma2(unsigned long long& acc,
                                     unsigned long long a,
                                     unsigned long long b) {
    asm("fma.rn.f32x2 %0, %1, %2, %0;" : "+l"(acc) : "l"(a), "l"(b));
}

// duplicate a scalar into both lanes of an f32x2 register
__device__ __forceinline__ unsigned long long pack2(float v) {
    unsigned long long r;
    asm("mov.b64 %0, {%1, %1};" : "=l"(r) : "f"(v));
    return r;
}

__global__ __launch_bounds__(BLOCK)
void anfis_kernel(const float* __restrict__ x,
                  const float* __restrict__ means,
                  const float* __restrict__ sigmas,
                  const float* __restrict__ cons_kp,
                  const float* __restrict__ cons_ki,
                  float* __restrict__ out) {
    // Interleaved consequent table: per rule 16 floats:
    // [kp0..kp6, 1.0, ki0..ki6, 0.0]  -> slot 7 accumulates wsum for free.
    __shared__ float cons_s[NUM_RULES * 16];   // 46656 B (< 48KB static limit)

    const int tid = threadIdx.x;
    for (int r = tid; r < NUM_RULES; r += BLOCK) {
        float* dst = cons_s + r * 16;
        #pragma unroll
        for (int j = 0; j < 7; j++) dst[j]     = cons_kp[r * 7 + j];
        dst[7] = 1.0f;
        #pragma unroll
        for (int j = 0; j < 7; j++) dst[8 + j] = cons_ki[r * 7 + j];
        dst[15] = 0.0f;
    }
    __syncthreads();

    const int b = blockIdx.x * BLOCK + tid;
    if (b >= B_TOTAL) return;

    // ---- load x row, compute 18 memberships ----
    float xv[NUM_IN];
    #pragma unroll
    for (int i = 0; i < NUM_IN; i++) xv[i] = x[b * NUM_IN + i];

    float mu[NUM_IN][NUM_MFS];
    #pragma unroll
    for (int i = 0; i < NUM_IN; i++) {
        #pragma unroll
        for (int m = 0; m < NUM_MFS; m++) {
            float t = __fdividef(xv[i] - means[i * NUM_MFS + m],
                                 sigmas[i * NUM_MFS + m] + 1e-6f);
            mu[i][m] = __expf(-0.5f * t * t);
        }
    }

    // ---- half-products of the base-3 rule structure ----
    // t012: read with runtime index (outer loop) -> local mem, 27 LDL total (cheap)
    float t012[27];
    #pragma unroll
    for (int a = 0; a < 3; a++)
        #pragma unroll
        for (int c = 0; c < 3; c++)
            #pragma unroll
            for (int d = 0; d < 3; d++)
                t012[a * 9 + c * 3 + d] = mu[0][a] * mu[1][c] * mu[2][d];

    // t345: only constant-indexed (inner loop fully unrolled) -> stays in registers
    float t345[27];
    #pragma unroll
    for (int a = 0; a < 3; a++)
        #pragma unroll
        for (int c = 0; c < 3; c++)
            #pragma unroll
            for (int d = 0; d < 3; d++)
                t345[a * 9 + c * 3 + d] = mu[3][a] * mu[4][c] * mu[5][d];

    // ---- main contraction: V[j] = sum_r w[r] * cons[r][j], wsum in slot 7 ----
    unsigned long long acc[8];
    #pragma unroll
    for (int j = 0; j < 8; j++) acc[j] = 0ull;

    #pragma unroll 1
    for (int o = 0; o < 27; o++) {
        const float q = t012[o];
        const ulonglong2* crow =
            reinterpret_cast<const ulonglong2*>(cons_s + o * 27 * 16);
        #pragma unroll
        for (int k = 0; k < 27; k++) {
            const float w = q * t345[k];
            const unsigned long long ww = pack2(w);
            // one rule = 64B = 4 broadcast LDS.128 (all lanes same addr)
            ulonglong2 c0 = crow[k * 4 + 0];
            ulonglong2 c1 = crow[k * 4 + 1];
            ulonglong2 c2 = crow[k * 4 + 2];
            ulonglong2 c3 = crow[k * 4 + 3];
            fma2(acc[0], ww, c0.x);
            fma2(acc[1], ww, c0.y);
            fma2(acc[2], ww, c1.x);
            fma2(acc[3], ww, c1.y);   // .y lane: w * 1.0 -> wsum
            fma2(acc[4], ww, c2.x);
            fma2(acc[5], ww, c2.y);
            fma2(acc[6], ww, c3.x);
            fma2(acc[7], ww, c3.y);
        }
    }

    // ---- unpack, final dot with x_bias, normalize ----
    float v[16];
    #pragma unroll
    for (int j = 0; j < 8; j++) {
        float2 u = *reinterpret_cast<float2*>(&acc[j]);
        v[2 * j]     = u.x;
        v[2 * j + 1] = u.y;
    }
    const float wsum = v[7];
    const float rden = 1.0f / (wsum + 1e-6f);

    float skp = v[6];        // kp bias coeff
    float ski = v[14];       // ki bias coeff
    #pragma unroll
    for (int j = 0; j < NUM_IN; j++) {
        skp = fmaf(xv[j], v[j],     skp);
        ski = fmaf(xv[j], v[8 + j], ski);
    }
    out[b * 2 + 0] = skp * rden;
    out[b * 2 + 1] = ski * rden;
}

extern "C" void kernel_launch(void* const* d_in, const int* in_sizes, int n_in,
                              void* d_out, int out_size) {
    const float* x       = (const float*)d_in[0];
    const float* means   = (const float*)d_in[1];
    const float* sigmas  = (const float*)d_in[2];
    const float* cons_kp = (const float*)d_in[3];
    const float* cons_ki = (const float*)d_in[4];
    // d_in[5] = rule_idx: deterministic base-3 digit table, hardcoded in-kernel.
    float* out = (float*)d_out;
    anfis_kernel<<<GRID, BLOCK>>>(x, means, sigmas, cons_kp, cons_ki, out);
}

// round 2
// speedup vs baseline: 1.1368x; 1.1368x over previous
#include <cuda_runtime.h>

#define B_TOTAL    32768
#define NUM_IN     6
#define NUM_MFS    3
#define NUM_RULES  729            // 3^6
#define BLOCK      128
#define GRID       128            // 128*128 threads * 2 rows = 32768 exactly

// packed f32x2 fma: acc = a*b + acc   (Blackwell fp32x2 pipe, 2 FMAs/instr)
__device__ __forceinline__ void fma2(unsigned long long& acc,
                                     unsigned long long a,
                                     unsigned long long b) {
    asm("fma.rn.f32x2 %0, %1, %2, %0;" : "+l"(acc) : "l"(a), "l"(b));
}

// duplicate a scalar into both lanes of an f32x2 register
__device__ __forceinline__ unsigned long long pack2(float v) {
    unsigned long long r;
    asm("mov.b64 %0, {%1, %1};" : "=l"(r) : "f"(v));
    return r;
}

__global__ __launch_bounds__(BLOCK)
void anfis_kernel(const float* __restrict__ x,
                  const float* __restrict__ means,
                  const float* __restrict__ sigmas,
                  const float* __restrict__ cons_kp,
                  const float* __restrict__ cons_ki,
                  float* __restrict__ out) {
    // Interleaved consequent table, per rule 16 floats:
    // [kp0..kp6, 1.0, ki0..ki6, 0.0]  -> slot 7 accumulates wsum for free.
    __shared__ float cons_s[NUM_RULES * 16];   // 46656 B

    const int tid = threadIdx.x;
    for (int r = tid; r < NUM_RULES; r += BLOCK) {
        float* dst = cons_s + r * 16;
        #pragma unroll
        for (int j = 0; j < 7; j++) dst[j]     = cons_kp[r * 7 + j];
        dst[7] = 1.0f;
        #pragma unroll
        for (int j = 0; j < 7; j++) dst[8 + j] = cons_ki[r * 7 + j];
        dst[15] = 0.0f;
    }
    __syncthreads();

    const int g  = blockIdx.x * BLOCK + tid;
    const int b0 = 2 * g;            // rows b0 and b0+1

    // ---- load both x rows (12 contiguous floats), compute 36 memberships ----
    float xv0[NUM_IN], xv1[NUM_IN];
    #pragma unroll
    for (int i = 0; i < NUM_IN; i++) xv0[i] = x[b0 * NUM_IN + i];
    #pragma unroll
    for (int i = 0; i < NUM_IN; i++) xv1[i] = x[(b0 + 1) * NUM_IN + i];

    float mu0[NUM_IN][NUM_MFS], mu1[NUM_IN][NUM_MFS];
    #pragma unroll
    for (int i = 0; i < NUM_IN; i++) {
        #pragma unroll
        for (int m = 0; m < NUM_MFS; m++) {
            const float rs = __fdividef(1.0f, sigmas[i * NUM_MFS + m] + 1e-6f);
            const float mn = means[i * NUM_MFS + m];
            float t0 = (xv0[i] - mn) * rs;
            float t1 = (xv1[i] - mn) * rs;
            mu0[i][m] = __expf(-0.5f * t0 * t0);
            mu1[i][m] = __expf(-0.5f * t1 * t1);
        }
    }

    // ---- half-products of the base-3 rule structure ----
    // t012: runtime-indexed by the (rolled) outer loop -> local mem (27 LDL each, cheap)
    float t012_0[27], t012_1[27];
    #pragma unroll
    for (int a = 0; a < 3; a++)
        #pragma unroll
        for (int c = 0; c < 3; c++)
            #pragma unroll
            for (int d = 0; d < 3; d++) {
                t012_0[a * 9 + c * 3 + d] = mu0[0][a] * mu0[1][c] * mu0[2][d];
                t012_1[a * 9 + c * 3 + d] = mu1[0][a] * mu1[1][c] * mu1[2][d];
            }

    // t345: constant-indexed only (inner loop fully unrolled) -> registers
    float t345_0[27], t345_1[27];
    #pragma unroll
    for (int a = 0; a < 3; a++)
        #pragma unroll
        for (int c = 0; c < 3; c++)
            #pragma unroll
            for (int d = 0; d < 3; d++) {
                t345_0[a * 9 + c * 3 + d] = mu0[3][a] * mu0[4][c] * mu0[5][d];
                t345_1[a * 9 + c * 3 + d] = mu1[3][a] * mu1[4][c] * mu1[5][d];
            }

    // ---- main contraction for both rows: V[j] = sum_r w[r] * cons[r][j] ----
    unsigned long long accA[8], accB[8];
    #pragma unroll
    for (int j = 0; j < 8; j++) { accA[j] = 0ull; accB[j] = 0ull; }

    #pragma unroll 1
    for (int o = 0; o < 27; o++) {
        const float q0 = t012_0[o];
        const float q1 = t012_1[o];
        const ulonglong2* crow =
            reinterpret_cast<const ulonglong2*>(cons_s + o * 27 * 16);
        #pragma unroll
        for (int k = 0; k < 27; k++) {
            const unsigned long long w0 = pack2(q0 * t345_0[k]);
            const unsigned long long w1 = pack2(q1 * t345_1[k]);
            // one rule = 64B = 4 broadcast LDS.128, reused by BOTH rows
            ulonglong2 c0 = crow[k * 4 + 0];
            ulonglong2 c1 = crow[k * 4 + 1];
            ulonglong2 c2 = crow[k * 4 + 2];
            ulonglong2 c3 = crow[k * 4 + 3];
            fma2(accA[0], w0, c0.x);  fma2(accB[0], w1, c0.x);
            fma2(accA[1], w0, c0.y);  fma2(accB[1], w1, c0.y);
            fma2(accA[2], w0, c1.x);  fma2(accB[2], w1, c1.x);
            fma2(accA[3], w0, c1.y);  fma2(accB[3], w1, c1.y);  // .y: wsum
            fma2(accA[4], w0, c2.x);  fma2(accB[4], w1, c2.x);
            fma2(accA[5], w0, c2.y);  fma2(accB[5], w1, c2.y);
            fma2(accA[6], w0, c3.x);  fma2(accB[6], w1, c3.x);
            fma2(accA[7], w0, c3.y);  fma2(accB[7], w1, c3.y);
        }
    }

    // ---- unpack, final dot with x_bias, normalize, vectorized store ----
    float vA[16], vB[16];
    #pragma unroll
    for (int j = 0; j < 8; j++) {
        float2 uA = *reinterpret_cast<float2*>(&accA[j]);
        float2 uB = *reinterpret_cast<float2*>(&accB[j]);
        vA[2 * j] = uA.x;  vA[2 * j + 1] = uA.y;
        vB[2 * j] = uB.x;  vB[2 * j + 1] = uB.y;
    }
    const float rdenA = 1.0f / (vA[7] + 1e-6f);
    const float rdenB = 1.0f / (vB[7] + 1e-6f);

    float skpA = vA[6], skiA = vA[14];
    float skpB = vB[6], skiB = vB[14];
    #pragma unroll
    for (int j = 0; j < NUM_IN; j++) {
        skpA = fmaf(xv0[j], vA[j],     skpA);
        skiA = fmaf(xv0[j], vA[8 + j], skiA);
        skpB = fmaf(xv1[j], vB[j],     skpB);
        skiB = fmaf(xv1[j], vB[8 + j], skiB);
    }

    float4 res;
    res.x = skpA * rdenA;
    res.y = skiA * rdenA;
    res.z = skpB * rdenB;
    res.w = skiB * rdenB;
    *reinterpret_cast<float4*>(out + 4 * g) = res;   // 16B-aligned, coalesced
}

extern "C" void kernel_launch(void* const* d_in, const int* in_sizes, int n_in,
                              void* d_out, int out_size) {
    const float* x       = (const float*)d_in[0];
    const float* means   = (const float*)d_in[1];
    const float* sigmas  = (const float*)d_in[2];
    const float* cons_kp = (const float*)d_in[3];
    const float* cons_ki = (const float*)d_in[4];
    // d_in[5] = rule_idx: deterministic base-3 digit table, hardcoded in-kernel.
    float* out = (float*)d_out;
    anfis_kernel<<<GRID, BLOCK>>>(x, means, sigmas, cons_kp, cons_ki, out);
}

// round 3
// speedup vs baseline: 1.1517x; 1.0130x over previous
#include <cuda_runtime.h>

#define B_TOTAL    32768
#define NUM_IN     6
#define NUM_MFS    3
#define NUM_RULES  729            // 3^6
#define BLOCK      384            // 3 teams x 128
#define GRID       128            // 128 CTAs * 128 lanes * 2 rows = 32768

typedef unsigned long long ull;

// packed f32x2 fma: acc = a*b + acc
__device__ __forceinline__ void fma2(ull& acc, ull a, ull b) {
    asm("fma.rn.f32x2 %0, %1, %2, %0;" : "+l"(acc) : "l"(a), "l"(b));
}
// packed f32x2 add: acc = acc + a
__device__ __forceinline__ void add2(ull& acc, ull a) {
    asm("add.rn.f32x2 %0, %0, %1;" : "+l"(acc) : "l"(a));
}
// duplicate a scalar into both lanes of an f32x2 register
__device__ __forceinline__ ull pack2(float v) {
    ull r;
    asm("mov.b64 %0, {%1, %1};" : "=l"(r) : "f"(v));
    return r;
}

__global__ __launch_bounds__(BLOCK)
void anfis_kernel(const float* __restrict__ x,
                  const float* __restrict__ means,
                  const float* __restrict__ sigmas,
                  const float* __restrict__ cons_kp,
                  const float* __restrict__ cons_ki,
                  float* __restrict__ out) {
    // Interleaved consequent table, per rule 16 floats:
    // [kp0..kp6, 1.0, ki0..ki6, 0.0]  -> slot 7 accumulates wsum for free.
    // After the main loop this buffer is reused as the reduction scratchpad.
    __shared__ __align__(16) float cons_s[NUM_RULES * 16];   // 46656 B

    const int tid  = threadIdx.x;
    const int team = tid >> 7;       // 0,1,2  (mu0 digit 'a' == team)
    const int lane = tid & 127;

    for (int r = tid; r < NUM_RULES; r += BLOCK) {
        float* dst = cons_s + r * 16;
        #pragma unroll
        for (int j = 0; j < 7; j++) dst[j]     = cons_kp[r * 7 + j];
        dst[7] = 1.0f;
        #pragma unroll
        for (int j = 0; j < 7; j++) dst[8 + j] = cons_ki[r * 7 + j];
        dst[15] = 0.0f;
    }
    __syncthreads();

    const int g  = blockIdx.x * 128 + lane;
    const int b0 = 2 * g;            // rows b0 and b0+1 (shared by all 3 teams)

    // ---- load both x rows, compute memberships ----
    float xv0[NUM_IN], xv1[NUM_IN];
    #pragma unroll
    for (int i = 0; i < NUM_IN; i++) xv0[i] = x[b0 * NUM_IN + i];
    #pragma unroll
    for (int i = 0; i < NUM_IN; i++) xv1[i] = x[(b0 + 1) * NUM_IN + i];

    // mu0: only the mf index == team is needed by this team
    float m0_0, m0_1;
    {
        const float rs = __fdividef(1.0f, sigmas[0 * NUM_MFS + team] + 1e-6f);
        const float mn = means[0 * NUM_MFS + team];
        float t0 = (xv0[0] - mn) * rs;
        float t1 = (xv1[0] - mn) * rs;
        m0_0 = __expf(-0.5f * t0 * t0);
        m0_1 = __expf(-0.5f * t1 * t1);
    }
    // mu1..mu5: all 3 mfs each
    float mu0[5][NUM_MFS], mu1[5][NUM_MFS];   // index i-1 for input i
    #pragma unroll
    for (int i = 1; i < NUM_IN; i++) {
        #pragma unroll
        for (int m = 0; m < NUM_MFS; m++) {
            const float rs = __fdividef(1.0f, sigmas[i * NUM_MFS + m] + 1e-6f);
            const float mn = means[i * NUM_MFS + m];
            float t0 = (xv0[i] - mn) * rs;
            float t1 = (xv1[i] - mn) * rs;
            mu0[i - 1][m] = __expf(-0.5f * t0 * t0);
            mu1[i - 1][m] = __expf(-0.5f * t1 * t1);
        }
    }

    // ---- team-local half products ----
    // q012[c*3+d] = mu0(team) * mu1(c) * mu2(d)   (9 per row, runtime-indexed -> LDL, cheap)
    float q012_0[9], q012_1[9];
    #pragma unroll
    for (int c = 0; c < 3; c++)
        #pragma unroll
        for (int d = 0; d < 3; d++) {
            q012_0[c * 3 + d] = m0_0 * mu0[0][c] * mu0[1][d];
            q012_1[c * 3 + d] = m0_1 * mu1[0][c] * mu1[1][d];
        }
    // t345: constant-indexed only -> registers
    float t345_0[27], t345_1[27];
    #pragma unroll
    for (int a = 0; a < 3; a++)
        #pragma unroll
        for (int c = 0; c < 3; c++)
            #pragma unroll
            for (int d = 0; d < 3; d++) {
                t345_0[a * 9 + c * 3 + d] = mu0[2][a] * mu0[3][c] * mu0[4][d];
                t345_1[a * 9 + c * 3 + d] = mu1[2][a] * mu1[3][c] * mu1[4][d];
            }

    // ---- contraction over this team's 243 rules ----
    ull accA[8], accB[8];
    #pragma unroll
    for (int j = 0; j < 8; j++) { accA[j] = 0ull; accB[j] = 0ull; }

    #pragma unroll 1
    for (int oo = 0; oo < 9; oo++) {
        const int o = team * 9 + oo;
        const float q0 = q012_0[oo];
        const float q1 = q012_1[oo];
        const ulonglong2* crow =
            reinterpret_cast<const ulonglong2*>(cons_s + o * 27 * 16);
        #pragma unroll
        for (int k = 0; k < 27; k++) {
            const ull w0 = pack2(q0 * t345_0[k]);
            const ull w1 = pack2(q1 * t345_1[k]);
            ulonglong2 c0 = crow[k * 4 + 0];
            ulonglong2 c1 = crow[k * 4 + 1];
            ulonglong2 c2 = crow[k * 4 + 2];
            ulonglong2 c3 = crow[k * 4 + 3];
            fma2(accA[0], w0, c0.x);  fma2(accB[0], w1, c0.x);
            fma2(accA[1], w0, c0.y);  fma2(accB[1], w1, c0.y);
            fma2(accA[2], w0, c1.x);  fma2(accB[2], w1, c1.x);
            fma2(accA[3], w0, c1.y);  fma2(accB[3], w1, c1.y);  // .y: wsum
            fma2(accA[4], w0, c2.x);  fma2(accB[4], w1, c2.x);
            fma2(accA[5], w0, c2.y);  fma2(accB[5], w1, c2.y);
            fma2(accA[6], w0, c3.x);  fma2(accB[6], w1, c3.x);
            fma2(accA[7], w0, c3.y);  fma2(accB[7], w1, c3.y);
        }
    }

    // ---- cross-team reduction (reuse cons_s as scratch) ----
    __syncthreads();                       // all reads of cons table done
    ull* red = reinterpret_cast<ull*>(cons_s);
    if (team > 0) {
        ull* dst = red + ((team - 1) * 128 + lane) * 16;
        #pragma unroll
        for (int j = 0; j < 8; j++) { dst[j] = accA[j]; dst[8 + j] = accB[j]; }
    }
    __syncthreads();

    if (team == 0) {
        const ull* p1 = red + lane * 16;
        const ull* p2 = red + (128 + lane) * 16;
        #pragma unroll
        for (int j = 0; j < 8; j++) {
            add2(accA[j], p1[j]);      add2(accA[j], p2[j]);
            add2(accB[j], p1[8 + j]);  add2(accB[j], p2[8 + j]);
        }

        float vA[16], vB[16];
        #pragma unroll
        for (int j = 0; j < 8; j++) {
            float2 uA = *reinterpret_cast<float2*>(&accA[j]);
            float2 uB = *reinterpret_cast<float2*>(&accB[j]);
            vA[2 * j] = uA.x;  vA[2 * j + 1] = uA.y;
            vB[2 * j] = uB.x;  vB[2 * j + 1] = uB.y;
        }
        const float rdenA = 1.0f / (vA[7] + 1e-6f);
        const float rdenB = 1.0f / (vB[7] + 1e-6f);

        float skpA = vA[6], skiA = vA[14];
        float skpB = vB[6], skiB = vB[14];
        #pragma unroll
        for (int j = 0; j < NUM_IN; j++) {
            skpA = fmaf(xv0[j], vA[j],     skpA);
            skiA = fmaf(xv0[j], vA[8 + j], skiA);
            skpB = fmaf(xv1[j], vB[j],     skpB);
            skiB = fmaf(xv1[j], vB[8 + j], skiB);
        }

        float4 res;
        res.x = skpA * rdenA;
        res.y = skiA * rdenA;
        res.z = skpB * rdenB;
        res.w = skiB * rdenB;
        *reinterpret_cast<float4*>(out + 4 * g) = res;   // coalesced
    }
}

extern "C" void kernel_launch(void* const* d_in, const int* in_sizes, int n_in,
                              void* d_out, int out_size) {
    const float* x       = (const float*)d_in[0];
    const float* means   = (const float*)d_in[1];
    const float* sigmas  = (const float*)d_in[2];
    const float* cons_kp = (const float*)d_in[3];
    const float* cons_ki = (const float*)d_in[4];
    // d_in[5] = rule_idx: deterministic base-3 digit table, hardcoded in-kernel.
    float* out = (float*)d_out;
    anfis_kernel<<<GRID, BLOCK>>>(x, means, sigmas, cons_kp, cons_ki, out);
}